// round 12
// baseline (speedup 1.0000x reference)
#include <cuda_runtime.h>
#include <cuda_fp16.h>
#include <math.h>
#include <stdint.h>

#define HIDDEN 1024
#define NE 16
#define NS 2
#define MID_R 256
#define MID_S 512
#define MAX_T 2048
#define BT 128
#define PADDED_CAP (MAX_T * 2 + NE * BT)    // 6144
#define N_TILES (PADDED_CAP / BT)           // 48

#define SAH 72                  // smem row stride in halves (144B, ldmatrix conflict-free)
#define ASTG (128 * SAH * 2)    // bytes per 128-row stage
#define BSTG (64 * SAH * 2)     // bytes per 64-row stage
#define GU_SMEM (2 * ASTG + 4 * BSTG + 1024)
#define DN_SMEM (4 * ASTG + 1024)

// ---------------- device scratch ----------------
__device__ __half h_x[MAX_T * HIDDEN];
__device__ __half h_wg_r[NE * MID_R * HIDDEN];   // [e][n][k]
__device__ __half h_wu_r[NE * MID_R * HIDDEN];
__device__ __half h_wd_r[NE * HIDDEN * MID_R];
__device__ __half h_wg_s[NS * MID_S * HIDDEN];
__device__ __half h_wu_s[NS * MID_S * HIDDEN];
__device__ __half h_wd_s[NS * HIDDEN * MID_S];
__device__ __half h_Hr[PADDED_CAP * MID_R];
__device__ __half h_Hs[NS * MAX_T * MID_S];
__device__ __half h_Y[PADDED_CAP * HIDDEN];
__device__ int    g_topk_idx[MAX_T][2];
__device__ float  g_topk_w[MAX_T][2];
__device__ int    g_off[NE + 1];
__device__ int    g_perm[PADDED_CAP];
__device__ float  g_pw[PADDED_CAP];
__device__ int    g_token_pos[MAX_T][2];
__device__ int    g_tile_expert[N_TILES];

// ---------------- helpers ----------------
__device__ __forceinline__ void mma16(float* c, const unsigned* a, const unsigned* b) {
    asm volatile(
        "mma.sync.aligned.m16n8k16.row.col.f32.f16.f16.f32 "
        "{%0,%1,%2,%3},{%4,%5,%6,%7},{%8,%9},{%0,%1,%2,%3};"
        : "+f"(c[0]), "+f"(c[1]), "+f"(c[2]), "+f"(c[3])
        : "r"(a[0]), "r"(a[1]), "r"(a[2]), "r"(a[3]), "r"(b[0]), "r"(b[1]));
}

__device__ __forceinline__ void ldsm4(unsigned* r, uint32_t a) {
    asm volatile("ldmatrix.sync.aligned.m8n8.x4.shared.b16 {%0,%1,%2,%3}, [%4];"
                 : "=r"(r[0]), "=r"(r[1]), "=r"(r[2]), "=r"(r[3]) : "r"(a));
}

__device__ __forceinline__ uint32_t smem_u32(const void* p) {
    uint32_t a;
    asm("{ .reg .u64 t; cvta.to.shared.u64 t, %1; cvt.u32.u64 %0, t; }" : "=r"(a) : "l"(p));
    return a;
}

#define CP16(d, s)      asm volatile("cp.async.cg.shared.global [%0], [%1], 16;" :: "r"(d), "l"(s))
#define CP16Z(d, s, n)  asm volatile("cp.async.cg.shared.global [%0], [%1], 16, %2;" :: "r"(d), "l"(s), "r"(n))
#define CPCOMMIT()      asm volatile("cp.async.commit_group;")
#define CPWAIT(n)       asm volatile("cp.async.wait_group %0;" :: "n"(n))

__device__ __forceinline__ float silu(float g) { return g / (1.f + __expf(-g)); }

// ---------------- router + x->fp16 convert (4 tokens per warp; no atomics) ----------------
__global__ void __launch_bounds__(256)
router_kernel(const float* __restrict__ x, const float* __restrict__ rw, int T) {
    int b = blockIdx.x;
    int tid = threadIdx.x, lane = tid & 31, w = tid >> 5;

    const float4* xb = (const float4*)(x + (size_t)b * 32 * HIDDEN);
    __half* hb = h_x + (size_t)b * 32 * HIDDEN;
#pragma unroll
    for (int i = 0; i < 32; i++) {
        int idx = tid + 256 * i;
        float4 v = __ldg(xb + idx);
        __half2 p0 = __floats2half2_rn(v.x, v.y), p1 = __floats2half2_rn(v.z, v.w);
        uint2 u;
        u.x = *(uint32_t*)&p0; u.y = *(uint32_t*)&p1;
        *(uint2*)(hb + (size_t)idx * 4) = u;
    }

    int tok0 = b * 32 + w * 4;
    const float* x0 = x + (size_t)tok0 * HIDDEN;

    float acc[4][NE];
#pragma unroll
    for (int t = 0; t < 4; t++)
#pragma unroll
        for (int e = 0; e < NE; e++) acc[t][e] = 0.f;

    for (int i = lane; i < HIDDEN; i += 32) {
        const float4* rp = (const float4*)(rw + (size_t)i * NE);
        float4 r0 = __ldg(rp + 0), r1 = __ldg(rp + 1);
        float4 r2 = __ldg(rp + 2), r3 = __ldg(rp + 3);
        float xs[4];
#pragma unroll
        for (int t = 0; t < 4; t++) xs[t] = __ldg(x0 + (size_t)t * HIDDEN + i);
#pragma unroll
        for (int t = 0; t < 4; t++) {
            float xv = xs[t];
            acc[t][0]  += xv * r0.x; acc[t][1]  += xv * r0.y; acc[t][2]  += xv * r0.z; acc[t][3]  += xv * r0.w;
            acc[t][4]  += xv * r1.x; acc[t][5]  += xv * r1.y; acc[t][6]  += xv * r1.z; acc[t][7]  += xv * r1.w;
            acc[t][8]  += xv * r2.x; acc[t][9]  += xv * r2.y; acc[t][10] += xv * r2.z; acc[t][11] += xv * r2.w;
            acc[t][12] += xv * r3.x; acc[t][13] += xv * r3.y; acc[t][14] += xv * r3.z; acc[t][15] += xv * r3.w;
        }
    }
#pragma unroll
    for (int t = 0; t < 4; t++)
#pragma unroll
        for (int e = 0; e < NE; e++)
#pragma unroll
            for (int o = 16; o > 0; o >>= 1)
                acc[t][e] += __shfl_xor_sync(0xffffffffu, acc[t][e], o);

    if (lane == 0) {
#pragma unroll
        for (int t = 0; t < 4; t++) {
            int tok = tok0 + t;
            float mx = acc[t][0];
#pragma unroll
            for (int e = 1; e < NE; e++) mx = fmaxf(mx, acc[t][e]);
            float p[NE], Z = 0.f;
#pragma unroll
            for (int e = 0; e < NE; e++) { p[e] = expf(acc[t][e] - mx); Z += p[e]; }
            int i1 = 0; float v1 = p[0];
#pragma unroll
            for (int e = 1; e < NE; e++) if (p[e] > v1) { v1 = p[e]; i1 = e; }
            int i2 = -1; float v2 = -1.f;
#pragma unroll
            for (int e = 0; e < NE; e++)
                if (e != i1 && p[e] > v2) { v2 = p[e]; i2 = e; }
            v1 /= Z; v2 /= Z;
            float s = v1 + v2 + 1e-9f;
            g_topk_idx[tok][0] = i1; g_topk_idx[tok][1] = i2;
            g_topk_w[tok][0] = v1 / s; g_topk_w[tok][1] = v2 / s;
        }
    }
}

// ---------------- fused dispatch ----------------
__global__ void __launch_bounds__(1024)
dispatch_k(int T) {
    __shared__ int sc[NE];
    __shared__ int soff[NE + 1];
    __shared__ int scur[NE];

    int tid = threadIdx.x;
    if (tid < NE) { sc[tid] = 0; scur[tid] = 0; }
    __syncthreads();

    for (int t = tid; t < T; t += 1024) {
        atomicAdd(&sc[g_topk_idx[t][0]], 1);
        atomicAdd(&sc[g_topk_idx[t][1]], 1);
    }
    __syncthreads();

    if (tid == 0) {
        int off = 0;
        for (int e = 0; e < NE; e++) {
            soff[e] = off;
            off += ((sc[e] + BT - 1) / BT) * BT;
        }
        soff[NE] = off;
    }
    __syncthreads();

    if (tid < NE + 1) g_off[tid] = soff[tid];
    if (tid < N_TILES) {
        int r = tid * BT;
        int e = NE - 1;
        for (int j = 0; j < NE; j++)
            if (r >= soff[j] && r < soff[j + 1]) e = j;
        g_tile_expert[tid] = e;
    }
    for (int i = tid; i < PADDED_CAP; i += 1024) { g_perm[i] = -1; g_pw[i] = 0.f; }
    __syncthreads();

    for (int t = tid; t < T; t += 1024) {
#pragma unroll
        for (int k = 0; k < 2; k++) {
            int e = g_topk_idx[t][k];
            int pos = soff[e] + atomicAdd(&scur[e], 1);
            g_perm[pos] = t;
            g_pw[pos] = g_topk_w[t][k];
            g_token_pos[t][k] = pos;
        }
    }
}

// ---------------- weights: fp32 [K][N] -> fp16 [N][K] ----------------
__global__ void __launch_bounds__(256)
transp_all_k(const float* __restrict__ wg_r, const float* __restrict__ wu_r,
             const float* __restrict__ wd_r, const float* __restrict__ wg_s,
             const float* __restrict__ wu_s, const float* __restrict__ wd_s) {
    __shared__ float ts[32][33];
    int b = blockIdx.x;
    const float* src; __half* dst; int K, N;
    if (b < 4096)        { src = wg_r; dst = h_wg_r; K = HIDDEN; N = MID_R; }
    else if (b < 8192)   { b -= 4096;  src = wu_r; dst = h_wu_r; K = HIDDEN; N = MID_R; }
    else if (b < 12288)  { b -= 8192;  src = wd_r; dst = h_wd_r; K = MID_R;  N = HIDDEN; }
    else if (b < 13312)  { b -= 12288; src = wg_s; dst = h_wg_s; K = HIDDEN; N = MID_S; }
    else if (b < 14336)  { b -= 13312; src = wu_s; dst = h_wu_s; K = HIDDEN; N = MID_S; }
    else                 { b -= 14336; src = wd_s; dst = h_wd_s; K = MID_S;  N = HIDDEN; }
    int tpe = (K / 32) * (N / 32);
    int e = b / tpe, t = b % tpe;
    int tk = t / (N / 32), tn = t % (N / 32);
    src += (size_t)e * K * N;
    dst += (size_t)e * K * N;

    int tid = threadIdx.x;
    int kr = tid >> 3, n4 = (tid & 7) << 2;
    float4 v = *(const float4*)(src + (size_t)(tk * 32 + kr) * N + tn * 32 + n4);
    ts[kr][n4 + 0] = v.x; ts[kr][n4 + 1] = v.y; ts[kr][n4 + 2] = v.z; ts[kr][n4 + 3] = v.w;
    __syncthreads();
    int nr = tid >> 3, k4 = (tid & 7) << 2;
    __half2 o0 = __floats2half2_rn(ts[k4 + 0][nr], ts[k4 + 1][nr]);
    __half2 o1 = __floats2half2_rn(ts[k4 + 2][nr], ts[k4 + 3][nr]);
    uint2 u;
    u.x = *(uint32_t*)&o0; u.y = *(uint32_t*)&o1;
    *(uint2*)(dst + (size_t)(tn * 32 + nr) * K + tk * 32 + k4) = u;
}

// =======================================================================
// gateup: 256 thr / 8 warps, 128x64 block tile, 32x32 warp tile (4x2),
// BK=64, cp.async.cg double-buffered, ldmatrix, mma16. (R9-proven)
// =======================================================================
__global__ void __launch_bounds__(256)
gateup_all_k() {
    const int NBR = N_TILES * (MID_R / 64);   // 192
    int b = blockIdx.x;

    bool routed;
    int row0, col0;
    const __half* Wg; const __half* Wu;
    __half* hbase; int hstride;

    if (b < NBR) {
        routed = true;
        int tile = b >> 2;
        col0 = (b & 3) * 64;
        row0 = tile * BT;
        if (row0 >= g_off[NE]) return;
        int e = g_tile_expert[tile];
        Wg = h_wg_r + (size_t)e * MID_R * HIDDEN;
        Wu = h_wu_r + (size_t)e * MID_R * HIDDEN;
        hbase = h_Hr; hstride = MID_R;
    } else {
        routed = false;
        b -= NBR;
        int n = b >> 7;
        int rem = b & 127;
        row0 = (rem >> 3) * BT;
        col0 = (rem & 7) * 64;
        Wg = h_wg_s + (size_t)n * MID_S * HIDDEN;
        Wu = h_wu_s + (size_t)n * MID_S * HIDDEN;
        hbase = h_Hs + (size_t)n * MAX_T * MID_S; hstride = MID_S;
    }

    extern __shared__ char dsm[];
    const uint32_t aAs = smem_u32(dsm);
    const uint32_t aBg = aAs + 2 * ASTG;
    const uint32_t aBu = aBg + 2 * BSTG;
    int*   s_perm = (int*)(dsm + 2 * ASTG + 4 * BSTG);
    float* s_pw   = (float*)(dsm + 2 * ASTG + 4 * BSTG + 512);

    int tid = threadIdx.x, lane = tid & 31, w = tid >> 5;
    int wr = w >> 1, wc = w & 1;
    int q2 = 2 * (lane & 3);
    uint32_t lrow = (lane & 15), lk = ((lane >> 4) << 3);
    const uint32_t aOffA = ((wr * 32 + lrow) * SAH + lk) * 2;
    const uint32_t aOffB = ((wc * 32 + lrow) * SAH + lk) * 2;

    if (routed && tid < BT) {
        s_perm[tid] = g_perm[row0 + tid];
        s_pw[tid] = g_pw[row0 + tid];
    }
    __syncthreads();

    float accg[2][4][4] = {}, accu[2][4][4] = {};

#define GU_LOADS(cc, st)                                                        \
    {                                                                           \
        int kk = (cc) * 64;                                                     \
        _Pragma("unroll")                                                       \
        for (int i = 0; i < 4; i++) {                                           \
            int idx = tid + 256 * i;                                            \
            int r = idx >> 3, c8 = (idx & 7) << 3;                              \
            uint32_t d = aAs + (st) * ASTG + (r * SAH + c8) * 2;                \
            if (routed) {                                                       \
                int grow = s_perm[r];                                           \
                const __half* sp = h_x + (size_t)(grow >= 0 ? grow : 0) * HIDDEN + kk + c8; \
                int pr = grow >= 0 ? 16 : 0;                                    \
                CP16Z(d, sp, pr);                                               \
            } else {                                                            \
                CP16(d, h_x + (size_t)(row0 + r) * HIDDEN + kk + c8);           \
            }                                                                   \
        }                                                                       \
        _Pragma("unroll")                                                       \
        for (int i = 0; i < 2; i++) {                                           \
            int idx = tid + 256 * i;                                            \
            int n = idx >> 3, c8 = (idx & 7) << 3;                              \
            CP16(aBg + (st) * BSTG + (n * SAH + c8) * 2,                        \
                 Wg + (size_t)(col0 + n) * HIDDEN + kk + c8);                   \
            CP16(aBu + (st) * BSTG + (n * SAH + c8) * 2,                        \
                 Wu + (size_t)(col0 + n) * HIDDEN + kk + c8);                   \
        }                                                                       \
    }

    const int NCH = HIDDEN / 64;   // 16
    GU_LOADS(0, 0)
    CPCOMMIT();

    for (int c = 0; c < NCH; c++) {
        int s = c & 1;
        if (c + 1 < NCH) {
            GU_LOADS(c + 1, s ^ 1)
            CPCOMMIT();
            CPWAIT(1);
        } else {
            CPWAIT(0);
        }
        __syncthreads();

        uint32_t aA = aAs + s * ASTG + aOffA;
        uint32_t aG = aBg + s * BSTG + aOffB;
        uint32_t aU = aBu + s * BSTG + aOffB;
#pragma unroll
        for (int ks = 0; ks < 4; ks++) {
            uint32_t koff = (uint32_t)(ks * 16) * 2;
            unsigned a[2][4], bg[2][4], bu[2][4];
#pragma unroll
            for (int rt = 0; rt < 2; rt++)
                ldsm4(a[rt], aA + rt * (16 * SAH * 2) + koff);
#pragma unroll
            for (int cp = 0; cp < 2; cp++) {
                ldsm4(bg[cp], aG + cp * (16 * SAH * 2) + koff);
                ldsm4(bu[cp], aU + cp * (16 * SAH * 2) + koff);
            }
#pragma unroll
            for (int rt = 0; rt < 2; rt++)
#pragma unroll
                for (int ct = 0; ct < 4; ct++) {
                    int cp = ct >> 1, wh = ct & 1;
                    unsigned bbg[2] = { bg[cp][wh], bg[cp][wh + 2] };
                    mma16(accg[rt][ct], a[rt], bbg);
                    unsigned bbu[2] = { bu[cp][wh], bu[cp][wh + 2] };
                    mma16(accu[rt][ct], a[rt], bbu);
                }
        }
        __syncthreads();
    }
#undef GU_LOADS

#pragma unroll
    for (int rt = 0; rt < 2; rt++) {
        int lr = wr * 32 + rt * 16 + (lane >> 2);
        float w0 = routed ? s_pw[lr] : 1.f;
        float w1 = routed ? s_pw[lr + 8] : 1.f;
#pragma unroll
        for (int ct = 0; ct < 4; ct++) {
            int c = col0 + wc * 32 + ct * 8 + q2;
            float* gg = accg[rt][ct];
            float* uu = accu[rt][ct];
            __half2 h0 = __floats2half2_rn(silu(gg[0]) * uu[0] * w0, silu(gg[1]) * uu[1] * w0);
            __half2 h1 = __floats2half2_rn(silu(gg[2]) * uu[2] * w1, silu(gg[3]) * uu[3] * w1);
            *(__half2*)(hbase + (size_t)(row0 + lr) * hstride + c) = h0;
            *(__half2*)(hbase + (size_t)(row0 + lr + 8) * hstride + c) = h1;
        }
    }
}

// =======================================================================
// down kernels: 256 thr / 8 warps, 128x128 block tile, 32x64 warp tile
// (warp grid 4x2), BK=64. ldsm/mma = 0.375.
// =======================================================================

// ---------------- routed down-proj -> h_Y (fp16) ----------------
__global__ void __launch_bounds__(256)
down_routed_k() {
    int tile = blockIdx.y;
    int row0 = tile * BT;
    if (row0 >= g_off[NE]) return;
    int col0 = blockIdx.x * 128;
    int e = g_tile_expert[tile];
    const __half* Wd = h_wd_r + (size_t)e * HIDDEN * MID_R;

    extern __shared__ char dsm[];
    const uint32_t aAs = smem_u32(dsm);
    const uint32_t aBs = aAs + 2 * ASTG;

    int tid = threadIdx.x, lane = tid & 31, w = tid >> 5;
    int wr = w >> 1, wc = w & 1;
    int q2 = 2 * (lane & 3);
    uint32_t lrow = (lane & 15), lk = ((lane >> 4) << 3);
    const uint32_t aOffA = ((wr * 32 + lrow) * SAH + lk) * 2;
    const uint32_t aOffB = ((wc * 64 + lrow) * SAH + lk) * 2;

    float acc[2][8][4] = {};

#define DR_LOADS(cc, st)                                                        \
    {                                                                           \
        int kk = (cc) * 64;                                                     \
        _Pragma("unroll")                                                       \
        for (int i = 0; i < 4; i++) {                                           \
            int idx = tid + 256 * i;                                            \
            int r = idx >> 3, c8 = (idx & 7) << 3;                              \
            uint32_t doff = (r * SAH + c8) * 2;                                 \
            CP16(aAs + (st) * ASTG + doff, h_Hr + (size_t)(row0 + r) * MID_R + kk + c8); \
            CP16(aBs + (st) * ASTG + doff, Wd + (size_t)(col0 + r) * MID_R + kk + c8);   \
        }                                                                       \
    }

    const int NCH = MID_R / 64;   // 4
    DR_LOADS(0, 0)
    CPCOMMIT();

    for (int c = 0; c < NCH; c++) {
        int s = c & 1;
        if (c + 1 < NCH) {
            DR_LOADS(c + 1, s ^ 1)
            CPCOMMIT();
            CPWAIT(1);
        } else {
            CPWAIT(0);
        }
        __syncthreads();

        uint32_t aA = aAs + s * ASTG + aOffA;
        uint32_t aB = aBs + s * ASTG + aOffB;
#pragma unroll
        for (int ks = 0; ks < 4; ks++) {
            uint32_t koff = (uint32_t)(ks * 16) * 2;
            unsigned a[2][4], bb[4][4];
#pragma unroll
            for (int rt = 0; rt < 2; rt++)
                ldsm4(a[rt], aA + rt * (16 * SAH * 2) + koff);
#pragma unroll
            for (int cp = 0; cp < 4; cp++)
                ldsm4(bb[cp], aB + cp * (16 * SAH * 2) + koff);
#pragma unroll
            for (int rt = 0; rt < 2; rt++)
#pragma unroll
                for (int ct = 0; ct < 8; ct++) {
                    int cp = ct >> 1, wh = ct & 1;
                    unsigned bf[2] = { bb[cp][wh], bb[cp][wh + 2] };
                    mma16(acc[rt][ct], a[rt], bf);
                }
        }
        __syncthreads();
    }
#undef DR_LOADS

#pragma unroll
    for (int rt = 0; rt < 2; rt++) {
        int r0 = row0 + wr * 32 + rt * 16 + (lane >> 2);
#pragma unroll
        for (int ct = 0; ct < 8; ct++) {
            int c = col0 + wc * 64 + ct * 8 + q2;
            __half2 y0 = __floats2half2_rn(acc[rt][ct][0], acc[rt][ct][1]);
            __half2 y1 = __floats2half2_rn(acc[rt][ct][2], acc[rt][ct][3]);
            *(__half2*)(h_Y + (size_t)r0 * HIDDEN + c) = y0;
            *(__half2*)(h_Y + (size_t)(r0 + 8) * HIDDEN + c) = y1;
        }
    }
}

// ---------------- shared down-proj + routed combine -> out ----------------
__global__ void __launch_bounds__(256)
down_shared_k(float* __restrict__ out) {
    int row0 = blockIdx.y * BT;
    int col0 = blockIdx.x * 128;

    extern __shared__ char dsm[];
    const uint32_t aAs = smem_u32(dsm);
    const uint32_t aBs = aAs + 2 * ASTG;
    int* s_p0 = (int*)(dsm + 4 * ASTG);
    int* s_p1 = (int*)(dsm + 4 * ASTG + 512);

    int tid = threadIdx.x, lane = tid & 31, w = tid >> 5;
    int wr = w >> 1, wc = w & 1;
    int q2 = 2 * (lane & 3);
    uint32_t lrow = (lane & 15), lk = ((lane >> 4) << 3);
    const uint32_t aOffA = ((wr * 32 + lrow) * SAH + lk) * 2;
    const uint32_t aOffB = ((wc * 64 + lrow) * SAH + lk) * 2;

    if (tid < BT) {
        s_p0[tid] = g_token_pos[row0 + tid][0];
        s_p1[tid] = g_token_pos[row0 + tid][1];
    }

    float acc[2][8][4] = {};

    const int CPE = MID_S / 64;     // 8
    const int NCH = NS * CPE;       // 16

#define DS_LOADS(cc, st)                                                        \
    {                                                                           \
        int nn = (cc) / CPE;                                                    \
        int kk = ((cc) % CPE) * 64;                                             \
        const __half* Asrc = h_Hs + (size_t)nn * MAX_T * MID_S;                 \
        const __half* Wd = h_wd_s + (size_t)nn * HIDDEN * MID_S;                \
        _Pragma("unroll")                                                       \
        for (int i = 0; i < 4; i++) {                                           \
            int idx = tid + 256 * i;                                            \
            int r = idx >> 3, c8 = (idx & 7) << 3;                              \
            uint32_t doff = (r * SAH + c8) * 2;                                 \
            CP16(aAs + (st) * ASTG + doff, Asrc + (size_t)(row0 + r) * MID_S + kk + c8); \
            CP16(aBs + (st) * ASTG + doff, Wd + (size_t)(col0 + r) * MID_S + kk + c8);   \
        }                                                                       \
    }

    DS_LOADS(0, 0)
    CPCOMMIT();

    for (int c = 0; c < NCH; c++) {
        int s = c & 1;
        if (c + 1 < NCH) {
            DS_LOADS(c + 1, s ^ 1)
            CPCOMMIT();
            CPWAIT(1);
        } else {
            CPWAIT(0);
        }
        __syncthreads();

        uint32_t aA = aAs + s * ASTG + aOffA;
        uint32_t aB = aBs + s * ASTG + aOffB;
#pragma unroll
        for (int ks = 0; ks < 4; ks++) {
            uint32_t koff = (uint32_t)(ks * 16) * 2;
            unsigned a[2][4], bb[4][4];
#pragma unroll
            for (int rt = 0; rt < 2; rt++)
                ldsm4(a[rt], aA + rt * (16 * SAH * 2) + koff);
#pragma unroll
            for (int cp = 0; cp < 4; cp++)
                ldsm4(bb[cp], aB + cp * (16 * SAH * 2) + koff);
#pragma unroll
            for (int rt = 0; rt < 2; rt++)
#pragma unroll
                for (int ct = 0; ct < 8; ct++) {
                    int cp = ct >> 1, wh = ct & 1;
                    unsigned bf[2] = { bb[cp][wh], bb[cp][wh + 2] };
                    mma16(acc[rt][ct], a[rt], bf);
                }
        }
        __syncthreads();
    }
#undef DS_LOADS

#pragma unroll
    for (int rt = 0; rt < 2; rt++) {
        int lr = wr * 32 + rt * 16 + (lane >> 2);
        int r0 = row0 + lr;
        int p0a = s_p0[lr], p1a = s_p1[lr];
        int p0b = s_p0[lr + 8], p1b = s_p1[lr + 8];
#pragma unroll
        for (int ct = 0; ct < 8; ct++) {
            int c = col0 + wc * 64 + ct * 8 + q2;
            float2 ya = __half22float2(*(const __half2*)(h_Y + (size_t)p0a * HIDDEN + c));
            float2 yb = __half22float2(*(const __half2*)(h_Y + (size_t)p1a * HIDDEN + c));
            *(float2*)(out + (size_t)r0 * HIDDEN + c) =
                make_float2(acc[rt][ct][0] + ya.x + yb.x,
                            acc[rt][ct][1] + ya.y + yb.y);
            float2 yc = __half22float2(*(const __half2*)(h_Y + (size_t)p0b * HIDDEN + c));
            float2 yd = __half22float2(*(const __half2*)(h_Y + (size_t)p1b * HIDDEN + c));
            *(float2*)(out + (size_t)(r0 + 8) * HIDDEN + c) =
                make_float2(acc[rt][ct][2] + yc.x + yd.x,
                            acc[rt][ct][3] + yc.y + yd.y);
        }
    }
}

// ---------------- launch ----------------
extern "C" void kernel_launch(void* const* d_in, const int* in_sizes, int n_in,
                              void* d_out, int out_size) {
    const float* x    = (const float*)d_in[0];
    const float* rw   = (const float*)d_in[1];
    const float* wg_r = (const float*)d_in[2];
    const float* wu_r = (const float*)d_in[3];
    const float* wd_r = (const float*)d_in[4];
    const float* wg_s = (const float*)d_in[5];
    const float* wu_s = (const float*)d_in[6];
    const float* wd_s = (const float*)d_in[7];
    float* out = (float*)d_out;

    int T = in_sizes[0] / HIDDEN;
    if (T > MAX_T || T % BT != 0) return;

    cudaFuncSetAttribute(gateup_all_k, cudaFuncAttributeMaxDynamicSharedMemorySize, GU_SMEM);
    cudaFuncSetAttribute(down_routed_k, cudaFuncAttributeMaxDynamicSharedMemorySize, DN_SMEM);
    cudaFuncSetAttribute(down_shared_k, cudaFuncAttributeMaxDynamicSharedMemorySize, DN_SMEM);

    router_kernel<<<T / 32, 256>>>(x, rw, T);
    dispatch_k<<<1, 1024>>>(T);
    transp_all_k<<<15360, 256>>>(wg_r, wu_r, wd_r, wg_s, wu_s, wd_s);

    int nb_gateup = N_TILES * (MID_R / 64)                 // 192 routed
                  + NS * (T / BT) * (MID_S / 64);          // 256 shared
    gateup_all_k<<<nb_gateup, 256, GU_SMEM>>>();           // 4th launch -> ncu lands here

    dim3 gdr(HIDDEN / 128, N_TILES);
    down_routed_k<<<gdr, 256, DN_SMEM>>>();

    dim3 gds(HIDDEN / 128, T / BT);
    down_shared_k<<<gds, 256, DN_SMEM>>>(out);
}

// round 13
// speedup vs baseline: 1.0176x; 1.0176x over previous
#include <cuda_runtime.h>
#include <cuda_fp16.h>
#include <math.h>
#include <stdint.h>

#define HIDDEN 1024
#define NE 16
#define NS 2
#define MID_R 256
#define MID_S 512
#define MAX_T 2048
#define BT 128
#define PADDED_CAP (MAX_T * 2 + NE * BT)    // 6144
#define N_TILES (PADDED_CAP / BT)           // 48

#define SAH 72            // smem row stride in halves (144B: 16B-aligned, ldmatrix conflict-free)
#define ASTG (128 * SAH * 2)   // bytes per A stage
#define BSTG (64 * SAH * 2)    // bytes per B stage
#define GU_SMEM (2 * ASTG + 4 * BSTG + 1024)
#define DN_SMEM (2 * ASTG + 2 * BSTG + 1024)

// ---------------- device scratch ----------------
__device__ __half h_x[MAX_T * HIDDEN];
__device__ __half h_wg_r[NE * MID_R * HIDDEN];   // [e][n][k]
__device__ __half h_wu_r[NE * MID_R * HIDDEN];
__device__ __half h_wd_r[NE * HIDDEN * MID_R];
__device__ __half h_wg_s[NS * MID_S * HIDDEN];
__device__ __half h_wu_s[NS * MID_S * HIDDEN];
__device__ __half h_wd_s[NS * HIDDEN * MID_S];
__device__ __half h_Hr[PADDED_CAP * MID_R];
__device__ __half h_Hs[NS * MAX_T * MID_S];
__device__ float  g_Y[PADDED_CAP][HIDDEN];
__device__ int    g_topk_idx[MAX_T][2];
__device__ float  g_topk_w[MAX_T][2];
__device__ int    g_off[NE + 1];
__device__ int    g_perm[PADDED_CAP];
__device__ float  g_pw[PADDED_CAP];
__device__ int    g_token_pos[MAX_T][2];
__device__ int    g_tile_expert[N_TILES];

// ---------------- helpers ----------------
__device__ __forceinline__ void mma16(float* c, const unsigned* a, const unsigned* b) {
    asm volatile(
        "mma.sync.aligned.m16n8k16.row.col.f32.f16.f16.f32 "
        "{%0,%1,%2,%3},{%4,%5,%6,%7},{%8,%9},{%0,%1,%2,%3};"
        : "+f"(c[0]), "+f"(c[1]), "+f"(c[2]), "+f"(c[3])
        : "r"(a[0]), "r"(a[1]), "r"(a[2]), "r"(a[3]), "r"(b[0]), "r"(b[1]));
}

__device__ __forceinline__ void ldsm4(unsigned* r, uint32_t a) {
    asm volatile("ldmatrix.sync.aligned.m8n8.x4.shared.b16 {%0,%1,%2,%3}, [%4];"
                 : "=r"(r[0]), "=r"(r[1]), "=r"(r[2]), "=r"(r[3]) : "r"(a));
}

__device__ __forceinline__ uint32_t smem_u32(const void* p) {
    uint32_t a;
    asm("{ .reg .u64 t; cvta.to.shared.u64 t, %1; cvt.u32.u64 %0, t; }" : "=r"(a) : "l"(p));
    return a;
}

#define CP16(d, s)      asm volatile("cp.async.ca.shared.global [%0], [%1], 16;" :: "r"(d), "l"(s))
#define CP16Z(d, s, n)  asm volatile("cp.async.ca.shared.global [%0], [%1], 16, %2;" :: "r"(d), "l"(s), "r"(n))
#define CPCOMMIT()      asm volatile("cp.async.commit_group;")
#define CPWAIT(n)       asm volatile("cp.async.wait_group %0;" :: "n"(n))

__device__ __forceinline__ float silu(float g) { return g / (1.f + __expf(-g)); }

// ---------------- router + x->fp16 convert (4 tokens per warp; no atomics) ----------------
__global__ void __launch_bounds__(256)
router_kernel(const float* __restrict__ x, const float* __restrict__ rw, int T) {
    int b = blockIdx.x;                      // 32 tokens per block
    int tid = threadIdx.x, lane = tid & 31, w = tid >> 5;

    const float4* xb = (const float4*)(x + (size_t)b * 32 * HIDDEN);
    __half* hb = h_x + (size_t)b * 32 * HIDDEN;
#pragma unroll
    for (int i = 0; i < 32; i++) {
        int idx = tid + 256 * i;
        float4 v = __ldg(xb + idx);
        __half2 p0 = __floats2half2_rn(v.x, v.y), p1 = __floats2half2_rn(v.z, v.w);
        uint2 u;
        u.x = *(uint32_t*)&p0; u.y = *(uint32_t*)&p1;
        *(uint2*)(hb + (size_t)idx * 4) = u;
    }

    int tok0 = b * 32 + w * 4;
    const float* x0 = x + (size_t)tok0 * HIDDEN;

    float acc[4][NE];
#pragma unroll
    for (int t = 0; t < 4; t++)
#pragma unroll
        for (int e = 0; e < NE; e++) acc[t][e] = 0.f;

    for (int i = lane; i < HIDDEN; i += 32) {
        const float4* rp = (const float4*)(rw + (size_t)i * NE);
        float4 r0 = __ldg(rp + 0), r1 = __ldg(rp + 1);
        float4 r2 = __ldg(rp + 2), r3 = __ldg(rp + 3);
        float xs[4];
#pragma unroll
        for (int t = 0; t < 4; t++) xs[t] = __ldg(x0 + (size_t)t * HIDDEN + i);
#pragma unroll
        for (int t = 0; t < 4; t++) {
            float xv = xs[t];
            acc[t][0]  += xv * r0.x; acc[t][1]  += xv * r0.y; acc[t][2]  += xv * r0.z; acc[t][3]  += xv * r0.w;
            acc[t][4]  += xv * r1.x; acc[t][5]  += xv * r1.y; acc[t][6]  += xv * r1.z; acc[t][7]  += xv * r1.w;
            acc[t][8]  += xv * r2.x; acc[t][9]  += xv * r2.y; acc[t][10] += xv * r2.z; acc[t][11] += xv * r2.w;
            acc[t][12] += xv * r3.x; acc[t][13] += xv * r3.y; acc[t][14] += xv * r3.z; acc[t][15] += xv * r3.w;
        }
    }
#pragma unroll
    for (int t = 0; t < 4; t++)
#pragma unroll
        for (int e = 0; e < NE; e++)
#pragma unroll
            for (int o = 16; o > 0; o >>= 1)
                acc[t][e] += __shfl_xor_sync(0xffffffffu, acc[t][e], o);

    if (lane == 0) {
#pragma unroll
        for (int t = 0; t < 4; t++) {
            int tok = tok0 + t;
            float mx = acc[t][0];
#pragma unroll
            for (int e = 1; e < NE; e++) mx = fmaxf(mx, acc[t][e]);
            float p[NE], Z = 0.f;
#pragma unroll
            for (int e = 0; e < NE; e++) { p[e] = expf(acc[t][e] - mx); Z += p[e]; }
            int i1 = 0; float v1 = p[0];
#pragma unroll
            for (int e = 1; e < NE; e++) if (p[e] > v1) { v1 = p[e]; i1 = e; }
            int i2 = -1; float v2 = -1.f;
#pragma unroll
            for (int e = 0; e < NE; e++)
                if (e != i1 && p[e] > v2) { v2 = p[e]; i2 = e; }
            v1 /= Z; v2 /= Z;
            float s = v1 + v2 + 1e-9f;
            g_topk_idx[tok][0] = i1; g_topk_idx[tok][1] = i2;
            g_topk_w[tok][0] = v1 / s; g_topk_w[tok][1] = v2 / s;
        }
    }
}

// ---------------- fused dispatch: histogram + offsets + tile map + pad init + scatter ----------------
__global__ void __launch_bounds__(1024)
dispatch_k(int T) {
    __shared__ int sc[NE];
    __shared__ int soff[NE + 1];
    __shared__ int scur[NE];

    int tid = threadIdx.x;
    if (tid < NE) { sc[tid] = 0; scur[tid] = 0; }
    __syncthreads();

    for (int t = tid; t < T; t += 1024) {
        atomicAdd(&sc[g_topk_idx[t][0]], 1);
        atomicAdd(&sc[g_topk_idx[t][1]], 1);
    }
    __syncthreads();

    if (tid == 0) {
        int off = 0;
        for (int e = 0; e < NE; e++) {
            soff[e] = off;
            off += ((sc[e] + BT - 1) / BT) * BT;
        }
        soff[NE] = off;
    }
    __syncthreads();

    if (tid < NE + 1) g_off[tid] = soff[tid];
    if (tid < N_TILES) {
        int r = tid * BT;
        int e = NE - 1;
        for (int j = 0; j < NE; j++)
            if (r >= soff[j] && r < soff[j + 1]) e = j;
        g_tile_expert[tid] = e;
    }
    for (int i = tid; i < PADDED_CAP; i += 1024) { g_perm[i] = -1; g_pw[i] = 0.f; }
    __syncthreads();

    for (int t = tid; t < T; t += 1024) {
#pragma unroll
        for (int k = 0; k < 2; k++) {
            int e = g_topk_idx[t][k];
            int pos = soff[e] + atomicAdd(&scur[e], 1);
            g_perm[pos] = t;
            g_pw[pos] = g_topk_w[t][k];
            g_token_pos[t][k] = pos;
        }
    }
}

// ---------------- weights: fp32 [K][N] -> fp16 [N][K] (tiled transpose) ----------------
__global__ void __launch_bounds__(256)
transp_all_k(const float* __restrict__ wg_r, const float* __restrict__ wu_r,
             const float* __restrict__ wd_r, const float* __restrict__ wg_s,
             const float* __restrict__ wu_s, const float* __restrict__ wd_s) {
    __shared__ float ts[32][33];
    int b = blockIdx.x;
    const float* src; __half* dst; int K, N;
    if (b < 4096)        { src = wg_r; dst = h_wg_r; K = HIDDEN; N = MID_R; }
    else if (b < 8192)   { b -= 4096;  src = wu_r; dst = h_wu_r; K = HIDDEN; N = MID_R; }
    else if (b < 12288)  { b -= 8192;  src = wd_r; dst = h_wd_r; K = MID_R;  N = HIDDEN; }
    else if (b < 13312)  { b -= 12288; src = wg_s; dst = h_wg_s; K = HIDDEN; N = MID_S; }
    else if (b < 14336)  { b -= 13312; src = wu_s; dst = h_wu_s; K = HIDDEN; N = MID_S; }
    else                 { b -= 14336; src = wd_s; dst = h_wd_s; K = MID_S;  N = HIDDEN; }
    int tpe = (K / 32) * (N / 32);
    int e = b / tpe, t = b % tpe;
    int tk = t / (N / 32), tn = t % (N / 32);
    src += (size_t)e * K * N;
    dst += (size_t)e * K * N;

    int tid = threadIdx.x;
    int kr = tid >> 3, n4 = (tid & 7) << 2;
    float4 v = *(const float4*)(src + (size_t)(tk * 32 + kr) * N + tn * 32 + n4);
    ts[kr][n4 + 0] = v.x; ts[kr][n4 + 1] = v.y; ts[kr][n4 + 2] = v.z; ts[kr][n4 + 3] = v.w;
    __syncthreads();
    int nr = tid >> 3, k4 = (tid & 7) << 2;
    __half2 o0 = __floats2half2_rn(ts[k4 + 0][nr], ts[k4 + 1][nr]);
    __half2 o1 = __floats2half2_rn(ts[k4 + 2][nr], ts[k4 + 3][nr]);
    uint2 u;
    u.x = *(uint32_t*)&o0; u.y = *(uint32_t*)&o1;
    *(uint2*)(dst + (size_t)(tn * 32 + nr) * K + tk * 32 + k4) = u;
}

// =======================================================================
// fp16 GEMMs: 256 thr / 8 warps, 128x64 block tile, 32x32 warp tile
// (warp grid 4x2), BK=64, cp.async double-buffered smem, ldmatrix, mma16.
// (R9-proven configuration — do not perturb.)
// =======================================================================

// ---------------- unified gate+up (routed + shared experts) ----------------
__global__ void __launch_bounds__(256)
gateup_all_k() {
    const int NBR = N_TILES * (MID_R / 64);   // 192
    int b = blockIdx.x;

    bool routed;
    int row0, col0;
    const __half* Wg; const __half* Wu;
    __half* hbase; int hstride;

    if (b < NBR) {
        routed = true;
        int tile = b >> 2;
        col0 = (b & 3) * 64;
        row0 = tile * BT;
        if (row0 >= g_off[NE]) return;
        int e = g_tile_expert[tile];
        Wg = h_wg_r + (size_t)e * MID_R * HIDDEN;
        Wu = h_wu_r + (size_t)e * MID_R * HIDDEN;
        hbase = h_Hr; hstride = MID_R;
    } else {
        routed = false;
        b -= NBR;
        int n = b >> 7;
        int rem = b & 127;
        row0 = (rem >> 3) * BT;
        col0 = (rem & 7) * 64;
        Wg = h_wg_s + (size_t)n * MID_S * HIDDEN;
        Wu = h_wu_s + (size_t)n * MID_S * HIDDEN;
        hbase = h_Hs + (size_t)n * MAX_T * MID_S; hstride = MID_S;
    }

    extern __shared__ char dsm[];
    const uint32_t aAs = smem_u32(dsm);
    const uint32_t aBg = aAs + 2 * ASTG;
    const uint32_t aBu = aBg + 2 * BSTG;
    int*   s_perm = (int*)(dsm + 2 * ASTG + 4 * BSTG);
    float* s_pw   = (float*)(dsm + 2 * ASTG + 4 * BSTG + 512);

    int tid = threadIdx.x, lane = tid & 31, w = tid >> 5;
    int wr = w >> 1, wc = w & 1;
    int q2 = 2 * (lane & 3);

    if (routed && tid < BT) {
        s_perm[tid] = g_perm[row0 + tid];
        s_pw[tid] = g_pw[row0 + tid];
    }
    __syncthreads();

    float accg[2][4][4] = {}, accu[2][4][4] = {};

#define GU_LOADS(cc, st)                                                        \
    {                                                                           \
        int kk = (cc) * 64;                                                     \
        _Pragma("unroll")                                                       \
        for (int i = 0; i < 4; i++) {                                           \
            int idx = tid + 256 * i;                                            \
            int r = idx >> 3, c8 = (idx & 7) << 3;                              \
            uint32_t d = aAs + (st) * ASTG + (r * SAH + c8) * 2;                \
            if (routed) {                                                       \
                int grow = s_perm[r];                                           \
                const __half* sp = h_x + (size_t)(grow >= 0 ? grow : 0) * HIDDEN + kk + c8; \
                int pr = grow >= 0 ? 16 : 0;                                    \
                CP16Z(d, sp, pr);                                               \
            } else {                                                            \
                CP16(d, h_x + (size_t)(row0 + r) * HIDDEN + kk + c8);           \
            }                                                                   \
        }                                                                       \
        _Pragma("unroll")                                                       \
        for (int i = 0; i < 2; i++) {                                           \
            int idx = tid + 256 * i;                                            \
            int n = idx >> 3, c8 = (idx & 7) << 3;                              \
            CP16(aBg + (st) * BSTG + (n * SAH + c8) * 2,                        \
                 Wg + (size_t)(col0 + n) * HIDDEN + kk + c8);                   \
            CP16(aBu + (st) * BSTG + (n * SAH + c8) * 2,                        \
                 Wu + (size_t)(col0 + n) * HIDDEN + kk + c8);                   \
        }                                                                       \
    }

    const int NCH = HIDDEN / 64;   // 16
    GU_LOADS(0, 0)
    CPCOMMIT();

    for (int c = 0; c < NCH; c++) {
        int s = c & 1;
        if (c + 1 < NCH) {
            GU_LOADS(c + 1, s ^ 1)
            CPCOMMIT();
            CPWAIT(1);
        } else {
            CPWAIT(0);
        }
        __syncthreads();

        uint32_t lrow = (lane & 15), lk = ((lane >> 4) << 3);
#pragma unroll
        for (int ks = 0; ks < 4; ks++) {
            int k0 = ks * 16;
            unsigned a[2][4], bg[2][4], bu[2][4];
#pragma unroll
            for (int rt = 0; rt < 2; rt++)
                ldsm4(a[rt], aAs + s * ASTG + ((wr * 32 + rt * 16 + lrow) * SAH + k0 + lk) * 2);
#pragma unroll
            for (int cp = 0; cp < 2; cp++) {
                ldsm4(bg[cp], aBg + s * BSTG + ((wc * 32 + cp * 16 + lrow) * SAH + k0 + lk) * 2);
                ldsm4(bu[cp], aBu + s * BSTG + ((wc * 32 + cp * 16 + lrow) * SAH + k0 + lk) * 2);
            }
#pragma unroll
            for (int rt = 0; rt < 2; rt++)
#pragma unroll
                for (int ct = 0; ct < 4; ct++) {
                    int cp = ct >> 1, wh = ct & 1;
                    unsigned bbg[2] = { bg[cp][wh], bg[cp][wh + 2] };
                    mma16(accg[rt][ct], a[rt], bbg);
                    unsigned bbu[2] = { bu[cp][wh], bu[cp][wh + 2] };
                    mma16(accu[rt][ct], a[rt], bbu);
                }
        }
        __syncthreads();
    }
#undef GU_LOADS

#pragma unroll
    for (int rt = 0; rt < 2; rt++) {
        int lr = wr * 32 + rt * 16 + (lane >> 2);
        float w0 = routed ? s_pw[lr] : 1.f;
        float w1 = routed ? s_pw[lr + 8] : 1.f;
#pragma unroll
        for (int ct = 0; ct < 4; ct++) {
            int c = col0 + wc * 32 + ct * 8 + q2;
            float* gg = accg[rt][ct];
            float* uu = accu[rt][ct];
            __half2 h0 = __floats2half2_rn(silu(gg[0]) * uu[0] * w0, silu(gg[1]) * uu[1] * w0);
            __half2 h1 = __floats2half2_rn(silu(gg[2]) * uu[2] * w1, silu(gg[3]) * uu[3] * w1);
            *(__half2*)(hbase + (size_t)(row0 + lr) * hstride + c) = h0;
            *(__half2*)(hbase + (size_t)(row0 + lr + 8) * hstride + c) = h1;
        }
    }
}

// ---------------- routed down-proj -> g_Y ----------------
__global__ void __launch_bounds__(256)
down_routed_k() {
    int tile = blockIdx.y;
    int row0 = tile * BT;
    if (row0 >= g_off[NE]) return;
    int col0 = blockIdx.x * 64;
    int e = g_tile_expert[tile];
    const __half* Wd = h_wd_r + (size_t)e * HIDDEN * MID_R;

    extern __shared__ char dsm[];
    const uint32_t aAs = smem_u32(dsm);
    const uint32_t aBs = aAs + 2 * ASTG;

    int tid = threadIdx.x, lane = tid & 31, w = tid >> 5;
    int wr = w >> 1, wc = w & 1;
    int q2 = 2 * (lane & 3);

    float acc[2][4][4] = {};

#define DR_LOADS(cc, st)                                                        \
    {                                                                           \
        int kk = (cc) * 64;                                                     \
        _Pragma("unroll")                                                       \
        for (int i = 0; i < 4; i++) {                                           \
            int idx = tid + 256 * i;                                            \
            int r = idx >> 3, c8 = (idx & 7) << 3;                              \
            CP16(aAs + (st) * ASTG + (r * SAH + c8) * 2,                        \
                 h_Hr + (size_t)(row0 + r) * MID_R + kk + c8);                  \
        }                                                                       \
        _Pragma("unroll")                                                       \
        for (int i = 0; i < 2; i++) {                                           \
            int idx = tid + 256 * i;                                            \
            int n = idx >> 3, c8 = (idx & 7) << 3;                              \
            CP16(aBs + (st) * BSTG + (n * SAH + c8) * 2,                        \
                 Wd + (size_t)(col0 + n) * MID_R + kk + c8);                    \
        }                                                                       \
    }

    const int NCH = MID_R / 64;   // 4
    DR_LOADS(0, 0)
    CPCOMMIT();

    for (int c = 0; c < NCH; c++) {
        int s = c & 1;
        if (c + 1 < NCH) {
            DR_LOADS(c + 1, s ^ 1)
            CPCOMMIT();
            CPWAIT(1);
        } else {
            CPWAIT(0);
        }
        __syncthreads();

        uint32_t lrow = (lane & 15), lk = ((lane >> 4) << 3);
#pragma unroll
        for (int ks = 0; ks < 4; ks++) {
            int k0 = ks * 16;
            unsigned a[2][4], bb[2][4];
#pragma unroll
            for (int rt = 0; rt < 2; rt++)
                ldsm4(a[rt], aAs + s * ASTG + ((wr * 32 + rt * 16 + lrow) * SAH + k0 + lk) * 2);
#pragma unroll
            for (int cp = 0; cp < 2; cp++)
                ldsm4(bb[cp], aBs + s * BSTG + ((wc * 32 + cp * 16 + lrow) * SAH + k0 + lk) * 2);
#pragma unroll
            for (int rt = 0; rt < 2; rt++)
#pragma unroll
                for (int ct = 0; ct < 4; ct++) {
                    int cp = ct >> 1, wh = ct & 1;
                    unsigned bf[2] = { bb[cp][wh], bb[cp][wh + 2] };
                    mma16(acc[rt][ct], a[rt], bf);
                }
        }
        __syncthreads();
    }
#undef DR_LOADS

#pragma unroll
    for (int rt = 0; rt < 2; rt++) {
        int r0 = row0 + wr * 32 + rt * 16 + (lane >> 2);
#pragma unroll
        for (int ct = 0; ct < 4; ct++) {
            int c = col0 + wc * 32 + ct * 8 + q2;
            *(float2*)&g_Y[r0][c] = make_float2(acc[rt][ct][0], acc[rt][ct][1]);
            *(float2*)&g_Y[r0 + 8][c] = make_float2(acc[rt][ct][2], acc[rt][ct][3]);
        }
    }
}

// ---------------- shared down-proj + routed combine -> out ----------------
__global__ void __launch_bounds__(256)
down_shared_k(float* __restrict__ out) {
    int row0 = blockIdx.y * BT;
    int col0 = blockIdx.x * 64;

    extern __shared__ char dsm[];
    const uint32_t aAs = smem_u32(dsm);
    const uint32_t aBs = aAs + 2 * ASTG;
    int* s_p0 = (int*)(dsm + 2 * ASTG + 2 * BSTG);
    int* s_p1 = (int*)(dsm + 2 * ASTG + 2 * BSTG + 512);

    int tid = threadIdx.x, lane = tid & 31, w = tid >> 5;
    int wr = w >> 1, wc = w & 1;
    int q2 = 2 * (lane & 3);

    if (tid < BT) {
        s_p0[tid] = g_token_pos[row0 + tid][0];
        s_p1[tid] = g_token_pos[row0 + tid][1];
    }

    float acc[2][4][4] = {};

    const int CPE = MID_S / 64;     // 8
    const int NCH = NS * CPE;       // 16

#define DS_LOADS(cc, st)                                                        \
    {                                                                           \
        int nn = (cc) / CPE;                                                    \
        int kk = ((cc) % CPE) * 64;                                             \
        const __half* Asrc = h_Hs + (size_t)nn * MAX_T * MID_S;                 \
        const __half* Wd = h_wd_s + (size_t)nn * HIDDEN * MID_S;                \
        _Pragma("unroll")                                                       \
        for (int i = 0; i < 4; i++) {                                           \
            int idx = tid + 256 * i;                                            \
            int r = idx >> 3, c8 = (idx & 7) << 3;                              \
            CP16(aAs + (st) * ASTG + (r * SAH + c8) * 2,                        \
                 Asrc + (size_t)(row0 + r) * MID_S + kk + c8);                  \
        }                                                                       \
        _Pragma("unroll")                                                       \
        for (int i = 0; i < 2; i++) {                                           \
            int idx = tid + 256 * i;                                            \
            int n = idx >> 3, c8 = (idx & 7) << 3;                              \
            CP16(aBs + (st) * BSTG + (n * SAH + c8) * 2,                        \
                 Wd + (size_t)(col0 + n) * MID_S + kk + c8);                    \
        }                                                                       \
    }

    DS_LOADS(0, 0)
    CPCOMMIT();

    for (int c = 0; c < NCH; c++) {
        int s = c & 1;
        if (c + 1 < NCH) {
            DS_LOADS(c + 1, s ^ 1)
            CPCOMMIT();
            CPWAIT(1);
        } else {
            CPWAIT(0);
        }
        __syncthreads();

        uint32_t lrow = (lane & 15), lk = ((lane >> 4) << 3);
#pragma unroll
        for (int ks = 0; ks < 4; ks++) {
            int k0 = ks * 16;
            unsigned a[2][4], bb[2][4];
#pragma unroll
            for (int rt = 0; rt < 2; rt++)
                ldsm4(a[rt], aAs + s * ASTG + ((wr * 32 + rt * 16 + lrow) * SAH + k0 + lk) * 2);
#pragma unroll
            for (int cp = 0; cp < 2; cp++)
                ldsm4(bb[cp], aBs + s * BSTG + ((wc * 32 + cp * 16 + lrow) * SAH + k0 + lk) * 2);
#pragma unroll
            for (int rt = 0; rt < 2; rt++)
#pragma unroll
                for (int ct = 0; ct < 4; ct++) {
                    int cp = ct >> 1, wh = ct & 1;
                    unsigned bf[2] = { bb[cp][wh], bb[cp][wh + 2] };
                    mma16(acc[rt][ct], a[rt], bf);
                }
        }
        __syncthreads();
    }
#undef DS_LOADS

#pragma unroll
    for (int rt = 0; rt < 2; rt++) {
        int lr = wr * 32 + rt * 16 + (lane >> 2);
        int r0 = row0 + lr;
        int p0a = s_p0[lr], p1a = s_p1[lr];
        int p0b = s_p0[lr + 8], p1b = s_p1[lr + 8];
#pragma unroll
        for (int ct = 0; ct < 4; ct++) {
            int c = col0 + wc * 32 + ct * 8 + q2;
            float2 ya = *(const float2*)&g_Y[p0a][c];
            float2 yb = *(const float2*)&g_Y[p1a][c];
            *(float2*)(out + (size_t)r0 * HIDDEN + c) =
                make_float2(acc[rt][ct][0] + ya.x + yb.x,
                            acc[rt][ct][1] + ya.y + yb.y);
            float2 yc = *(const float2*)&g_Y[p0b][c];
            float2 yd = *(const float2*)&g_Y[p1b][c];
            *(float2*)(out + (size_t)(r0 + 8) * HIDDEN + c) =
                make_float2(acc[rt][ct][2] + yc.x + yd.x,
                            acc[rt][ct][3] + yc.y + yd.y);
        }
    }
}

// ---------------- launch ----------------
extern "C" void kernel_launch(void* const* d_in, const int* in_sizes, int n_in,
                              void* d_out, int out_size) {
    const float* x    = (const float*)d_in[0];
    const float* rw   = (const float*)d_in[1];
    const float* wg_r = (const float*)d_in[2];
    const float* wu_r = (const float*)d_in[3];
    const float* wd_r = (const float*)d_in[4];
    const float* wg_s = (const float*)d_in[5];
    const float* wu_s = (const float*)d_in[6];
    const float* wd_s = (const float*)d_in[7];
    float* out = (float*)d_out;

    int T = in_sizes[0] / HIDDEN;
    if (T > MAX_T || T % BT != 0) return;

    cudaFuncSetAttribute(gateup_all_k, cudaFuncAttributeMaxDynamicSharedMemorySize, GU_SMEM);
    cudaFuncSetAttribute(down_routed_k, cudaFuncAttributeMaxDynamicSharedMemorySize, DN_SMEM);
    cudaFuncSetAttribute(down_shared_k, cudaFuncAttributeMaxDynamicSharedMemorySize, DN_SMEM);

    // Fork a side stream (created per call, leaked: host-side only, no device
    // allocation) so the weight transpose overlaps router+dispatch. The
    // event-based fork/join keeps the whole thing graph-capturable.
    cudaStream_t s2;
    cudaEvent_t e1, e2;
    cudaStreamCreateWithFlags(&s2, cudaStreamNonBlocking);
    cudaEventCreateWithFlags(&e1, cudaEventDisableTiming);
    cudaEventCreateWithFlags(&e2, cudaEventDisableTiming);

    cudaEventRecord(e1, 0);                    // fork point on capture (default) stream
    cudaStreamWaitEvent(s2, e1, 0);
    transp_all_k<<<15360, 256, 0, s2>>>(wg_r, wu_r, wd_r, wg_s, wu_s, wd_s);
    cudaEventRecord(e2, s2);                   // join marker

    router_kernel<<<T / 32, 256>>>(x, rw, T);  // default stream, overlaps transp
    dispatch_k<<<1, 1024>>>(T);

    cudaStreamWaitEvent(0, e2, 0);             // join before GEMMs need weights

    int nb_gateup = N_TILES * (MID_R / 64)                 // 192 routed
                  + NS * (T / BT) * (MID_S / 64);          // 256 shared
    gateup_all_k<<<nb_gateup, 256, GU_SMEM>>>();

    dim3 gdr(HIDDEN / 64, N_TILES);
    down_routed_k<<<gdr, 256, DN_SMEM>>>();

    dim3 gds(HIDDEN / 64, T / BT);
    down_shared_k<<<gds, 256, DN_SMEM>>>(out);
}